// round 5
// baseline (speedup 1.0000x reference)
#include <cuda_runtime.h>

// URPE: out[b,h,i,j] = probs[b,h,i,j] * toe[h,i,j]
// toe[h,i,j] = (j>=i) ? w[h, 2048 + (j-i)] : w[h, i-j]
// B=2, H=16, L=2048, weights (16, 4096) f32.
//
// 4 rows (same b,h) per block: amortizes block turnover, index math and the
// L2-hit Toeplitz gather over 64 KB of DRAM traffic instead of 16 KB, and
// deepens per-thread MLP (8 outstanding LDG.128). Default cache policy
// (streaming hints measured 10us slower on sm_103a).

#define L_DIM 2048
#define ROWS_PER_BLK 4

__global__ __launch_bounds__(256, 7)
void urpe_kernel(const float4* __restrict__ probs,
                 const float* __restrict__ w,
                 float4* __restrict__ out)
{
    __shared__ float toe_row[ROWS_PER_BLK][L_DIM];

    const unsigned int blk = blockIdx.x;              // 16384 blocks
    const unsigned int row0 = blk * ROWS_PER_BLK;     // ((b*16+h)*2048 + i0)
    const int i0 = (int)(row0 & 2047u);               // i0 % 4 == 0
    const int h  = (int)((row0 >> 11) & 15u);
    const float* __restrict__ wh = w + h * (2 * L_DIM);

    const int tid = threadIdx.x;
    const unsigned long long base = (unsigned long long)row0 * 512ull;

    // 1) Launch all 8 DRAM loads for this block up front (max MLP).
    float4 v[2 * ROWS_PER_BLK];
    #pragma unroll
    for (int r = 0; r < ROWS_PER_BLK; ++r) {
        v[2 * r]     = probs[base + r * 512 + tid];
        v[2 * r + 1] = probs[base + r * 512 + tid + 256];
    }

    // 2) Gather the 4 Toeplitz rows from L2 into smem (coalesced).
    #pragma unroll
    for (int r = 0; r < ROWS_PER_BLK; ++r) {
        int i = i0 + r;
        #pragma unroll
        for (int j = tid; j < L_DIM; j += 256) {
            int d = j - i;
            toe_row[r][j] = __ldg(&wh[d >= 0 ? 2048 + d : -d]);
        }
    }
    __syncthreads();

    // 3) Multiply + store.
    #pragma unroll
    for (int r = 0; r < ROWS_PER_BLK; ++r) {
        const float4* __restrict__ toe4 = (const float4*)toe_row[r];
        float4 t0 = toe4[tid];
        float4 t1 = toe4[tid + 256];
        float4 a = v[2 * r], b = v[2 * r + 1];
        float4 r0, r1;
        r0.x = a.x * t0.x;  r0.y = a.y * t0.y;
        r0.z = a.z * t0.z;  r0.w = a.w * t0.w;
        r1.x = b.x * t1.x;  r1.y = b.y * t1.y;
        r1.z = b.z * t1.z;  r1.w = b.w * t1.w;
        out[base + r * 512 + tid]       = r0;
        out[base + r * 512 + tid + 256] = r1;
    }
}

extern "C" void kernel_launch(void* const* d_in, const int* in_sizes, int n_in,
                              void* d_out, int out_size)
{
    const float4* probs = (const float4*)d_in[0];   // (2,16,2048,2048) f32
    const float*  w     = (const float*)d_in[1];    // (16, 4096) f32
    float4* out = (float4*)d_out;

    // 65536 rows / 4 rows per block = 16384 blocks
    urpe_kernel<<<16384, 256>>>(probs, w, out);
}

// round 6
// speedup vs baseline: 1.2213x; 1.2213x over previous
#include <cuda_runtime.h>

// URPE: out[b,h,i,j] = probs[b,h,i,j] * toe[h,i,j]
// toe[h,i,j] = (j>=i) ? w[h, 2048 + (j-i)] : w[h, i-j]
// B=2, H=16, L=2048, weights (16, 4096) f32.
//
// One block per (h,i) pair, serving BOTH batch entries: the Toeplitz row is
// b-independent, so one smem fill covers 32 KB of DRAM traffic. This halves
// the weight gather traffic through L1/LTS (was equal to the probs read
// itself) without raising register pressure or per-thread MLP (the R5
// 4-row/8-LDG variant regressed via L1tex-queue spread + occupancy loss).
// Default cache policy (streaming hints measured 10us slower on sm_103a).

#define L_DIM 2048
#define B_STRIDE_F4 (16ull * 2048ull * 512ull)   // one batch in float4 units

__global__ __launch_bounds__(256, 8)
void urpe_kernel(const float4* __restrict__ probs,
                 const float* __restrict__ w,
                 float4* __restrict__ out)
{
    __shared__ float toe_row[L_DIM];

    const unsigned int blk = blockIdx.x;          // h*2048 + i, 32768 blocks
    const int i = (int)(blk & 2047u);
    const int h = (int)(blk >> 11);
    const float* __restrict__ wh = w + h * (2 * L_DIM);

    const int tid = threadIdx.x;

    // Gather the Toeplitz row from L1/L2 into smem (coalesced, contiguous).
    #pragma unroll
    for (int j = tid; j < L_DIM; j += 256) {
        int d = j - i;
        toe_row[j] = __ldg(&wh[d >= 0 ? 2048 + d : -d]);
    }
    __syncthreads();

    const float4* __restrict__ toe4 = (const float4*)toe_row;
    const float4 t0 = toe4[tid];
    const float4 t1 = toe4[tid + 256];

    const unsigned long long base = (unsigned long long)blk * 512ull;

    // Both batch entries share this toe row.
    #pragma unroll
    for (int b = 0; b < 2; ++b) {
        const unsigned long long o = base + b * B_STRIDE_F4;
        float4 v0 = probs[o + tid];
        float4 v1 = probs[o + tid + 256];
        float4 r0, r1;
        r0.x = v0.x * t0.x;  r0.y = v0.y * t0.y;
        r0.z = v0.z * t0.z;  r0.w = v0.w * t0.w;
        r1.x = v1.x * t1.x;  r1.y = v1.y * t1.y;
        r1.z = v1.z * t1.z;  r1.w = v1.w * t1.w;
        out[o + tid]       = r0;
        out[o + tid + 256] = r1;
    }
}

extern "C" void kernel_launch(void* const* d_in, const int* in_sizes, int n_in,
                              void* d_out, int out_size)
{
    const float4* probs = (const float4*)d_in[0];   // (2,16,2048,2048) f32
    const float*  w     = (const float*)d_in[1];    // (16, 4096) f32
    float4* out = (float4*)d_out;

    // 16*2048 = 32768 (h,i) blocks; each handles b=0 and b=1
    urpe_kernel<<<32768, 256>>>(probs, w, out);
}

// round 8
// speedup vs baseline: 1.2231x; 1.0014x over previous
#include <cuda_runtime.h>

// URPE: out[b,h,i,j] = probs[b,h,i,j] * toe[h,i,j]
// toe[h,i,j] = (j>=i) ? w[h, 2048 + (j-i)] : w[h, i-j]
// B=2, H=16, L=2048, weights (16, 4096) f32.
//
// One block per (h,i) pair, serving BOTH batch entries (toe row is
// b-independent; one smem fill covers 32 KB of DRAM traffic). All four
// probs LDG.128 are front-batched before any store so b=1's reads overlap
// b=0's writebacks (MLP_p1=4; the MLP_p1=8 variant regressed via
// L1tex-queue spread). Default cache policy (streaming hints measured
// 10us slower on sm_103a). Measured plateau: ~6.77 TB/s, 85% DRAM — three
// different structures all land here; this is the mixed-R/W HBM ceiling.

#define L_DIM 2048
#define B_STRIDE_F4 (16ull * 2048ull * 512ull)   // one batch in float4 units

__global__ __launch_bounds__(256, 8)
void urpe_kernel(const float4* __restrict__ probs,
                 const float* __restrict__ w,
                 float4* __restrict__ out)
{
    __shared__ float toe_row[L_DIM];

    const unsigned int blk = blockIdx.x;          // h*2048 + i, 32768 blocks
    const int i = (int)(blk & 2047u);
    const int h = (int)(blk >> 11);
    const float* __restrict__ wh = w + h * (2 * L_DIM);

    const int tid = threadIdx.x;
    const unsigned long long base = (unsigned long long)blk * 512ull;
    const unsigned long long o0 = base;
    const unsigned long long o1 = base + B_STRIDE_F4;

    // Front-batch all 4 DRAM loads (independent of smem; max overlap with
    // the L2-hit weight gather below).
    float4 v0 = probs[o0 + tid];
    float4 v1 = probs[o0 + tid + 256];
    float4 v2 = probs[o1 + tid];
    float4 v3 = probs[o1 + tid + 256];

    // Gather the Toeplitz row from L1/L2 into smem (coalesced, contiguous).
    #pragma unroll
    for (int j = tid; j < L_DIM; j += 256) {
        int d = j - i;
        toe_row[j] = __ldg(&wh[d >= 0 ? 2048 + d : -d]);
    }
    __syncthreads();

    const float4* __restrict__ toe4 = (const float4*)toe_row;
    const float4 t0 = toe4[tid];
    const float4 t1 = toe4[tid + 256];

    float4 r0, r1, r2, r3;
    r0.x = v0.x * t0.x;  r0.y = v0.y * t0.y;
    r0.z = v0.z * t0.z;  r0.w = v0.w * t0.w;
    r1.x = v1.x * t1.x;  r1.y = v1.y * t1.y;
    r1.z = v1.z * t1.z;  r1.w = v1.w * t1.w;
    r2.x = v2.x * t0.x;  r2.y = v2.y * t0.y;
    r2.z = v2.z * t0.z;  r2.w = v2.w * t0.w;
    r3.x = v3.x * t1.x;  r3.y = v3.y * t1.y;
    r3.z = v3.z * t1.z;  r3.w = v3.w * t1.w;

    out[o0 + tid]       = r0;
    out[o0 + tid + 256] = r1;
    out[o1 + tid]       = r2;
    out[o1 + tid + 256] = r3;
}

extern "C" void kernel_launch(void* const* d_in, const int* in_sizes, int n_in,
                              void* d_out, int out_size)
{
    const float4* probs = (const float4*)d_in[0];   // (2,16,2048,2048) f32
    const float*  w     = (const float*)d_in[1];    // (16, 4096) f32
    float4* out = (float4*)d_out;

    // 16*2048 = 32768 (h,i) blocks; each handles b=0 and b=1
    urpe_kernel<<<32768, 256>>>(probs, w, out);
}

// round 9
// speedup vs baseline: 1.2343x; 1.0092x over previous
#include <cuda_runtime.h>

// URPE: out[b,h,i,j] = probs[b,h,i,j] * toe[h,i,j]
// toe[h,i,j] = (j>=i) ? w[h, 2048 + (j-i)] : w[h, i-j]
// B=2, H=16, L=2048, weights (16, 4096) f32.
//
// One 512-thread block per (h,i) pair, serving BOTH batch entries (toe row
// is b-independent -> one smem fill per 32 KB of DRAM traffic). Each thread
// owns exactly one float4 column for both batches: 4 LDG.128 front-batched,
// 4 STG.128. Final-form kernel at the measured roofline: four structural
// variants all plateau at ~6.77 TB/s (85% DRAM) -- the sm_103a mixed
// 1:1 R/W HBM3e ceiling. Streaming cache hints measured 10us SLOWER
// (evict-first defeats L2 writeback coalescing); deeper per-thread MLP
// (8 LDG.128) measured 34us slower (L1tex-queue spread + occupancy loss).

#define L_DIM 2048
#define B_STRIDE_F4 (16ull * 2048ull * 512ull)   // one batch in float4 units

__global__ __launch_bounds__(512, 4)
void urpe_kernel(const float4* __restrict__ probs,
                 const float* __restrict__ w,
                 float4* __restrict__ out)
{
    __shared__ float toe_row[L_DIM];

    const unsigned int blk = blockIdx.x;          // h*2048 + i, 32768 blocks
    const int i = (int)(blk & 2047u);
    const int h = (int)(blk >> 11);
    const float* __restrict__ wh = w + h * (2 * L_DIM);

    const int tid = threadIdx.x;                  // [0,512): one float4 column
    const unsigned long long base = (unsigned long long)blk * 512ull;
    const unsigned long long o0 = base + tid;
    const unsigned long long o1 = base + B_STRIDE_F4 + tid;

    // Front-batch both DRAM loads (independent of the smem fill below).
    float4 v0 = probs[o0];
    float4 v1 = probs[o1];

    // Gather the Toeplitz row from L1/L2 into smem (coalesced, contiguous).
    #pragma unroll
    for (int j = tid; j < L_DIM; j += 512) {
        int d = j - i;
        toe_row[j] = __ldg(&wh[d >= 0 ? 2048 + d : -d]);
    }
    __syncthreads();

    const float4 t = ((const float4*)toe_row)[tid];

    float4 r0, r1;
    r0.x = v0.x * t.x;  r0.y = v0.y * t.y;
    r0.z = v0.z * t.z;  r0.w = v0.w * t.w;
    r1.x = v1.x * t.x;  r1.y = v1.y * t.y;
    r1.z = v1.z * t.z;  r1.w = v1.w * t.w;

    out[o0] = r0;
    out[o1] = r1;
}

extern "C" void kernel_launch(void* const* d_in, const int* in_sizes, int n_in,
                              void* d_out, int out_size)
{
    const float4* probs = (const float4*)d_in[0];   // (2,16,2048,2048) f32
    const float*  w     = (const float*)d_in[1];    // (16, 4096) f32
    float4* out = (float4*)d_out;

    // 16*2048 = 32768 (h,i) blocks; each handles b=0 and b=1
    urpe_kernel<<<32768, 512>>>(probs, w, out);
}